// round 7
// baseline (speedup 1.0000x reference)
#include <cuda_runtime.h>
#include <cuda_bf16.h>
#include <math.h>

// Problem constants (fixed by the dataset)
#define NMAX 100000
#define EMAX 1600000
#define TMAX (NMAX + EMAX)
#define INF 128
#define HID 64

// ---------------- scratch (device globals; no allocation allowed) ------------
// Invariant: g_agg, g_denom, g_colsum are ZERO on entry to kernel_launch
// (zero at module load; each consuming pass re-zeroes them for the next replay).
__device__ __align__(128) __nv_bfloat16 g_hb[(size_t)NMAX * HID]; // 12.8 MB
__device__ __align__(128) float g_agg[(size_t)NMAX * HID];        // 25.6 MB
__device__ __align__(128) float g_asrc[NMAX];
__device__ __align__(128) float g_adst[NMAX];
__device__ __align__(128) float g_denom[NMAX];
__device__ __align__(128) float g_colsum[HID];

// ---------------- vector reduction helper ------------------------------------
__device__ __forceinline__ void red_add_v4(float* p, float a, float b, float c, float d) {
    asm volatile("red.global.add.v4.f32 [%0], {%1, %2, %3, %4};"
                 :: "l"(p), "f"(a), "f"(b), "f"(c), "f"(d) : "memory");
}

// ---------------- GEMM: h = x @ W (bf16 out), fused attention scores ---------
// Block tile 128x64, 256 threads, 8x4 per thread. Scores from fp32 accumulators.
__global__ __launch_bounds__(256) void gemm_kernel(
    const float* __restrict__ x, const float* __restrict__ W,
    const float* __restrict__ att_src, const float* __restrict__ att_dst, int N)
{
    __shared__ float xs[32][129];
    __shared__ float ws[32][64];

    const int tid = threadIdx.x;
    const int cx  = tid & 15;
    const int ry  = tid >> 4;
    const int rowBase = blockIdx.x * 128;

    float acc[8][4];
#pragma unroll
    for (int i = 0; i < 8; i++)
#pragma unroll
        for (int c = 0; c < 4; c++) acc[i][c] = 0.f;

    float as4[4], ad4[4];
#pragma unroll
    for (int c = 0; c < 4; c++) {
        as4[c] = att_src[cx * 4 + c];
        ad4[c] = att_dst[cx * 4 + c];
    }

    for (int kc = 0; kc < INF; kc += 32) {
#pragma unroll
        for (int idx = tid; idx < 128 * 32; idx += 256) {
            int r = idx >> 5, k = idx & 31;
            int gr = rowBase + r;
            xs[k][r] = (gr < N) ? x[(size_t)gr * INF + kc + k] : 0.f;
        }
#pragma unroll
        for (int idx = tid; idx < 32 * 64; idx += 256) {
            int k = idx >> 6, j = idx & 63;
            ws[k][j] = W[(size_t)(kc + k) * HID + j];
        }
        __syncthreads();

#pragma unroll
        for (int k = 0; k < 32; k++) {
            float4 wv = *(const float4*)&ws[k][cx * 4];
#pragma unroll
            for (int i = 0; i < 8; i++) {
                float xv = xs[k][ry + 16 * i];
                acc[i][0] += xv * wv.x;
                acc[i][1] += xv * wv.y;
                acc[i][2] += xv * wv.z;
                acc[i][3] += xv * wv.w;
            }
        }
        __syncthreads();
    }

#pragma unroll
    for (int i = 0; i < 8; i++) {
        int r = rowBase + ry + 16 * i;
        if (r < N) {
            // pack 4 fp32 -> 4 bf16 (8 bytes) and store
            __nv_bfloat162 p0 = __floats2bfloat162_rn(acc[i][0], acc[i][1]);
            __nv_bfloat162 p1 = __floats2bfloat162_rn(acc[i][2], acc[i][3]);
            uint2 pk;
            pk.x = *(const unsigned int*)&p0;
            pk.y = *(const unsigned int*)&p1;
            ((uint2*)g_hb)[(size_t)r * 16 + cx] = pk;

            float ps = acc[i][0] * as4[0] + acc[i][1] * as4[1] +
                       acc[i][2] * as4[2] + acc[i][3] * as4[3];
            float pd = acc[i][0] * ad4[0] + acc[i][1] * ad4[1] +
                       acc[i][2] * ad4[2] + acc[i][3] * ad4[3];
#pragma unroll
            for (int o = 8; o; o >>= 1) {
                ps += __shfl_xor_sync(0xFFFFFFFFu, ps, o);
                pd += __shfl_xor_sync(0xFFFFFFFFu, pd, o);
            }
            if (cx == 0) { g_asrc[r] = ps; g_adst[r] = pd; }
        }
    }
}

// ---------------- single edge pass (bf16 h gather, fp32 RED) ------------------
// 8 lanes per edge (4 edges per warp). One LDG.128 per lane covers the full
// 128-byte bf16 row; 2 red.v4 fp32 per lane into agg[dst].
// w = exp(leaky_relu(a_src[s]+a_dst[d])) (max-shift omitted: logits O(10),
// alpha shift-invariant, fp32-safe). denom[d] += w from sub-lane 0.
__global__ __launch_bounds__(256) void edge_kernel(
    const int* __restrict__ ei, int E, int N)
{
    const int T = E + N;
    const int lane = threadIdx.x & 31;
    const int oct  = lane >> 3;
    const int sub  = lane & 7;

    long long warpId = ((long long)blockIdx.x * blockDim.x + threadIdx.x) >> 5;
    long long e = warpId * 4 + oct;
    if (e >= T) return;

    int s, d;
    if (e < E) { s = ei[e]; d = ei[E + e]; }
    else       { s = d = (int)(e - E); }

    float l = g_asrc[s] + g_adst[d];
    l = (l > 0.f) ? l : 0.2f * l;
    float w = expf(l);

    // 16B = 8 bf16 features: f = sub*8 .. sub*8+7
    float4 raw = __ldg(&((const float4*)g_hb)[(size_t)s * 8 + sub]);
    const __nv_bfloat162* pr = (const __nv_bfloat162*)&raw;
    float2 f0 = __bfloat1622float2(pr[0]);
    float2 f1 = __bfloat1622float2(pr[1]);
    float2 f2 = __bfloat1622float2(pr[2]);
    float2 f3 = __bfloat1622float2(pr[3]);

    float* ap = g_agg + (size_t)d * HID + sub * 8;
    red_add_v4(ap,     w * f0.x, w * f0.y, w * f1.x, w * f1.y);
    red_add_v4(ap + 4, w * f2.x, w * f2.y, w * f3.x, w * f3.y);

    if (sub == 0) atomicAdd(&g_denom[d], w);
}

// ---------------- colsum of relu(agg/denom + bias); re-zeroes agg+denom ------
// float4 per thread, 16 rows in flight per block iteration.
__global__ __launch_bounds__(256) void colsum_kernel(
    const float* __restrict__ bias, int N)
{
    const int c  = threadIdx.x & 15;    // float4 column group
    const int rg = threadIdx.x >> 4;    // row sub-group 0..15
    const unsigned grpMask = 0xFFFFu << ((rg & 1) * 16);  // my 16-thread group

    float4 b = ((const float4*)bias)[c];
    float4 acc = make_float4(0.f, 0.f, 0.f, 0.f);
    float4* __restrict__ agg4 = (float4*)g_agg;
    const float4 zero4 = make_float4(0.f, 0.f, 0.f, 0.f);

    for (int r = blockIdx.x * 16 + rg; r < N; r += gridDim.x * 16) {
        float inv = 1.f / g_denom[r];
        size_t idx = (size_t)r * 16 + c;
        float4 v = agg4[idx];
        agg4[idx] = zero4;                    // re-zero agg for next replay
        __syncwarp(grpMask);                  // all 16 have read denom[r]
        if (c == 0) g_denom[r] = 0.f;         // re-zero denom for next replay
        acc.x += fmaxf(v.x * inv + b.x, 0.f);
        acc.y += fmaxf(v.y * inv + b.y, 0.f);
        acc.z += fmaxf(v.z * inv + b.z, 0.f);
        acc.w += fmaxf(v.w * inv + b.w, 0.f);
    }

    __shared__ float sm[16][64];
    sm[rg][c * 4 + 0] = acc.x;
    sm[rg][c * 4 + 1] = acc.y;
    sm[rg][c * 4 + 2] = acc.z;
    sm[rg][c * 4 + 3] = acc.w;
    __syncthreads();
    if (threadIdx.x < 64) {
        float s = 0.f;
#pragma unroll
        for (int g = 0; g < 16; g++) s += sm[g][threadIdx.x];
        atomicAdd(&g_colsum[threadIdx.x], s);
    }
}

// ---------------- final: out = (colsum/N) @ W_lin + b_lin; reset colsum ------
__global__ void final_kernel(const float* __restrict__ W_lin,
                             const float* __restrict__ b_lin,
                             float* __restrict__ out, float invN)
{
    int j = threadIdx.x;   // 64 threads
    float acc = b_lin[j];
#pragma unroll
    for (int k = 0; k < 64; k++)
        acc += (g_colsum[k] * invN) * W_lin[k * 64 + j];
    out[j] = acc;
    __syncthreads();
    g_colsum[j] = 0.f;     // reset for next replay
}

// ---------------- launch -----------------------------------------------------
extern "C" void kernel_launch(void* const* d_in, const int* in_sizes, int n_in,
                              void* d_out, int out_size)
{
    const float* x       = (const float*)d_in[0];
    const int*   ei      = (const int*)d_in[1];
    const float* W       = (const float*)d_in[2];
    const float* att_src = (const float*)d_in[3];
    const float* att_dst = (const float*)d_in[4];
    const float* bias    = (const float*)d_in[5];
    const float* W_lin   = (const float*)d_in[6];
    const float* b_lin   = (const float*)d_in[7];
    float*       out     = (float*)d_out;

    const int N = in_sizes[0] / INF;       // 100000
    const int E = in_sizes[1] / 2;         // 1600000
    const int T = E + N;

    gemm_kernel<<<(N + 127) / 128, 256>>>(x, W, att_src, att_dst, N);

    long long warps = ((long long)T + 3) / 4;          // 4 edges per warp
    long long threads = warps * 32;
    int blocks = (int)((threads + 255) / 256);
    edge_kernel<<<blocks, 256>>>(ei, E, N);

    colsum_kernel<<<1024, 256>>>(bias, N);

    final_kernel<<<1, 64>>>(W_lin, b_lin, out, 1.0f / (float)N);
}

// round 9
// speedup vs baseline: 1.1788x; 1.1788x over previous
#include <cuda_runtime.h>
#include <cuda_bf16.h>
#include <math.h>

// Problem constants (fixed by the dataset)
#define NMAX 100000
#define EMAX 1600000
#define TMAX (NMAX + EMAX)
#define INF 128
#define HID 64

// ---------------- scratch (device globals; no allocation allowed) ------------
// Invariant: g_agg, g_denom, g_colsum, g_done are ZERO on entry to kernel_launch
// (zero at module load; each consuming pass re-zeroes them for the next replay).
__device__ __align__(128) __nv_bfloat16 g_hb[(size_t)NMAX * HID]; // 12.8 MB
__device__ __align__(128) float g_agg[(size_t)NMAX * HID];        // 25.6 MB
__device__ __align__(128) float g_asrc[NMAX];
__device__ __align__(128) float g_adst[NMAX];
__device__ __align__(128) float g_denom[NMAX];
__device__ __align__(128) float g_colsum[HID];
__device__ unsigned int g_done;

// ---------------- vector reduction helper ------------------------------------
__device__ __forceinline__ void red_add_v4(float* p, float a, float b, float c, float d) {
    asm volatile("red.global.add.v4.f32 [%0], {%1, %2, %3, %4};"
                 :: "l"(p), "f"(a), "f"(b), "f"(c), "f"(d) : "memory");
}

// ---------------- GEMM: h = x @ W (bf16 out), fused attention scores ---------
// Block tile 128x64, 256 threads, 8x4 per thread. Scores from fp32 accumulators.
__global__ __launch_bounds__(256) void gemm_kernel(
    const float* __restrict__ x, const float* __restrict__ W,
    const float* __restrict__ att_src, const float* __restrict__ att_dst, int N)
{
    __shared__ float xs[32][129];
    __shared__ float ws[32][64];

    const int tid = threadIdx.x;
    const int cx  = tid & 15;
    const int ry  = tid >> 4;
    const int rowBase = blockIdx.x * 128;

    float acc[8][4];
#pragma unroll
    for (int i = 0; i < 8; i++)
#pragma unroll
        for (int c = 0; c < 4; c++) acc[i][c] = 0.f;

    float as4[4], ad4[4];
#pragma unroll
    for (int c = 0; c < 4; c++) {
        as4[c] = att_src[cx * 4 + c];
        ad4[c] = att_dst[cx * 4 + c];
    }

    for (int kc = 0; kc < INF; kc += 32) {
#pragma unroll
        for (int idx = tid; idx < 128 * 32; idx += 256) {
            int r = idx >> 5, k = idx & 31;
            int gr = rowBase + r;
            xs[k][r] = (gr < N) ? x[(size_t)gr * INF + kc + k] : 0.f;
        }
#pragma unroll
        for (int idx = tid; idx < 32 * 64; idx += 256) {
            int k = idx >> 6, j = idx & 63;
            ws[k][j] = W[(size_t)(kc + k) * HID + j];
        }
        __syncthreads();

#pragma unroll
        for (int k = 0; k < 32; k++) {
            float4 wv = *(const float4*)&ws[k][cx * 4];
#pragma unroll
            for (int i = 0; i < 8; i++) {
                float xv = xs[k][ry + 16 * i];
                acc[i][0] += xv * wv.x;
                acc[i][1] += xv * wv.y;
                acc[i][2] += xv * wv.z;
                acc[i][3] += xv * wv.w;
            }
        }
        __syncthreads();
    }

#pragma unroll
    for (int i = 0; i < 8; i++) {
        int r = rowBase + ry + 16 * i;
        if (r < N) {
            // pack 4 fp32 -> 4 bf16 (8 bytes) and store
            __nv_bfloat162 p0 = __floats2bfloat162_rn(acc[i][0], acc[i][1]);
            __nv_bfloat162 p1 = __floats2bfloat162_rn(acc[i][2], acc[i][3]);
            uint2 pk;
            pk.x = *(const unsigned int*)&p0;
            pk.y = *(const unsigned int*)&p1;
            ((uint2*)g_hb)[(size_t)r * 16 + cx] = pk;

            float ps = acc[i][0] * as4[0] + acc[i][1] * as4[1] +
                       acc[i][2] * as4[2] + acc[i][3] * as4[3];
            float pd = acc[i][0] * ad4[0] + acc[i][1] * ad4[1] +
                       acc[i][2] * ad4[2] + acc[i][3] * ad4[3];
#pragma unroll
            for (int o = 8; o; o >>= 1) {
                ps += __shfl_xor_sync(0xFFFFFFFFu, ps, o);
                pd += __shfl_xor_sync(0xFFFFFFFFu, pd, o);
            }
            if (cx == 0) { g_asrc[r] = ps; g_adst[r] = pd; }
        }
    }
}

// ---------------- single edge pass (bf16 h gather, fp32 RED) ------------------
// 8 lanes per edge (4 edges per warp). Lane sub loads features [sub*4..sub*4+3]
// and [32+sub*4..+3] (two 8B bf16 chunks, same 128B row line) and REDs them at
// ap+sub*4 / ap+32+sub*4 -> each red.v4 warp-op covers ONE contiguous 128B
// sector across the 8 lanes (1 LTS wavefront per RED, same layout as R5).
// w = exp(leaky_relu(a_src[s]+a_dst[d])) (max-shift omitted: logits O(10),
// alpha shift-invariant, fp32-safe). denom[d] += w from sub-lane 0.
__global__ __launch_bounds__(256) void edge_kernel(
    const int* __restrict__ ei, int E, int N)
{
    const int T = E + N;
    const int lane = threadIdx.x & 31;
    const int oct  = lane >> 3;
    const int sub  = lane & 7;

    long long warpId = ((long long)blockIdx.x * blockDim.x + threadIdx.x) >> 5;
    long long e = warpId * 4 + oct;
    if (e >= T) return;

    int s, d;
    if (e < E) { s = ei[e]; d = ei[E + e]; }
    else       { s = d = (int)(e - E); }

    float l = g_asrc[s] + g_adst[d];
    l = (l > 0.f) ? l : 0.2f * l;
    float w = expf(l);

    const uint2* __restrict__ hrow = (const uint2*)(g_hb + (size_t)s * HID);
    uint2 l0 = __ldg(&hrow[sub]);        // features sub*4 .. sub*4+3
    uint2 l1 = __ldg(&hrow[sub + 8]);    // features 32+sub*4 .. +3

    float2 a0 = __bfloat1622float2(*(const __nv_bfloat162*)&l0.x);
    float2 a1 = __bfloat1622float2(*(const __nv_bfloat162*)&l0.y);
    float2 b0 = __bfloat1622float2(*(const __nv_bfloat162*)&l1.x);
    float2 b1 = __bfloat1622float2(*(const __nv_bfloat162*)&l1.y);

    float* ap = g_agg + (size_t)d * HID;
    red_add_v4(ap + sub * 4,      w * a0.x, w * a0.y, w * a1.x, w * a1.y);
    red_add_v4(ap + 32 + sub * 4, w * b0.x, w * b0.y, w * b1.x, w * b1.y);

    if (sub == 0) atomicAdd(&g_denom[d], w);
}

// ---------------- colsum + fused final ---------------------------------------
// colsum of relu(agg/denom + bias); re-zeroes agg+denom. Last block computes
// out = (colsum/N) @ W_lin + b_lin and resets colsum + done counter.
__global__ __launch_bounds__(256) void colsum_kernel(
    const float* __restrict__ bias,
    const float* __restrict__ W_lin, const float* __restrict__ b_lin,
    float* __restrict__ out, float invN, int N)
{
    const int c  = threadIdx.x & 15;    // float4 column group
    const int rg = threadIdx.x >> 4;    // row sub-group 0..15
    const unsigned grpMask = 0xFFFFu << ((rg & 1) * 16);  // my 16-thread group

    float4 b = ((const float4*)bias)[c];
    float4 acc = make_float4(0.f, 0.f, 0.f, 0.f);
    float4* __restrict__ agg4 = (float4*)g_agg;
    const float4 zero4 = make_float4(0.f, 0.f, 0.f, 0.f);

    for (int r = blockIdx.x * 16 + rg; r < N; r += gridDim.x * 16) {
        float inv = 1.f / g_denom[r];
        size_t idx = (size_t)r * 16 + c;
        float4 v = agg4[idx];
        agg4[idx] = zero4;                    // re-zero agg for next replay
        __syncwarp(grpMask);                  // all 16 have read denom[r]
        if (c == 0) g_denom[r] = 0.f;         // re-zero denom for next replay
        acc.x += fmaxf(v.x * inv + b.x, 0.f);
        acc.y += fmaxf(v.y * inv + b.y, 0.f);
        acc.z += fmaxf(v.z * inv + b.z, 0.f);
        acc.w += fmaxf(v.w * inv + b.w, 0.f);
    }

    __shared__ float sm[16][64];
    sm[rg][c * 4 + 0] = acc.x;
    sm[rg][c * 4 + 1] = acc.y;
    sm[rg][c * 4 + 2] = acc.z;
    sm[rg][c * 4 + 3] = acc.w;
    __syncthreads();
    if (threadIdx.x < 64) {
        float s = 0.f;
#pragma unroll
        for (int g = 0; g < 16; g++) s += sm[g][threadIdx.x];
        atomicAdd(&g_colsum[threadIdx.x], s);
    }

    // ---- last-block final matvec ----
    __shared__ bool isLast;
    __threadfence();
    __syncthreads();
    if (threadIdx.x == 0) {
        unsigned v = atomicAdd(&g_done, 1u);
        isLast = (v == gridDim.x - 1);
    }
    __syncthreads();
    if (isLast) {
        int j = threadIdx.x;
        if (j < 64) {
            float a = b_lin[j];
#pragma unroll
            for (int k = 0; k < 64; k++)
                a += (g_colsum[k] * invN) * W_lin[k * 64 + j];
            out[j] = a;
        }
        __syncthreads();
        if (j < 64) g_colsum[j] = 0.f;   // reset for next replay
        if (j == 0) g_done = 0u;          // reset counter
    }
}

// ---------------- launch -----------------------------------------------------
extern "C" void kernel_launch(void* const* d_in, const int* in_sizes, int n_in,
                              void* d_out, int out_size)
{
    const float* x       = (const float*)d_in[0];
    const int*   ei      = (const int*)d_in[1];
    const float* W       = (const float*)d_in[2];
    const float* att_src = (const float*)d_in[3];
    const float* att_dst = (const float*)d_in[4];
    const float* bias    = (const float*)d_in[5];
    const float* W_lin   = (const float*)d_in[6];
    const float* b_lin   = (const float*)d_in[7];
    float*       out     = (float*)d_out;

    const int N = in_sizes[0] / INF;       // 100000
    const int E = in_sizes[1] / 2;         // 1600000
    const int T = E + N;

    gemm_kernel<<<(N + 127) / 128, 256>>>(x, W, att_src, att_dst, N);

    long long warps = ((long long)T + 3) / 4;          // 4 edges per warp
    long long threads = warps * 32;
    int blocks = (int)((threads + 255) / 256);
    edge_kernel<<<blocks, 256>>>(ei, E, N);

    colsum_kernel<<<1024, 256>>>(bias, W_lin, b_lin, out, 1.0f / (float)N, N);
}

// round 11
// speedup vs baseline: 1.5897x; 1.3486x over previous
#include <cuda_runtime.h>
#include <cuda_bf16.h>
#include <math.h>

// Problem constants (fixed by the dataset)
#define NMAX 100000
#define EMAX 1600000
#define TMAX (NMAX + EMAX)
#define INF 128
#define HID 64

// ---------------- scratch (device globals; no allocation allowed) ------------
// Invariant: g_aggh, g_denom, g_colsum, g_done are ZERO on entry to
// kernel_launch (zero at module load; each consuming pass re-zeroes them).
__device__ __align__(128) __nv_bfloat16 g_hb[(size_t)NMAX * HID];   // 12.8 MB
__device__ __align__(128) __nv_bfloat16 g_aggh[(size_t)NMAX * HID]; // 12.8 MB
__device__ __align__(128) float g_asrc[NMAX];
__device__ __align__(128) float g_adst[NMAX];
__device__ __align__(128) float g_denom[NMAX];
__device__ __align__(128) float g_colsum[HID];
__device__ unsigned int g_done;

// ---------------- GEMM: h = x @ W (bf16 out), fused attention scores ---------
// Block tile 128x64, 256 threads. Thread (cx,ry) computes 8 CONTIGUOUS rows
// ry*8..ry*8+7 x 4 cols -> xs reads become 2x LDS.128 (broadcast) per k.
__global__ __launch_bounds__(256) void gemm_kernel(
    const float* __restrict__ x, const float* __restrict__ W,
    const float* __restrict__ att_src, const float* __restrict__ att_dst, int N)
{
    __shared__ float xs[32][132];   // pad 132: rows 16B-aligned for LDS.128
    __shared__ float ws[32][64];

    const int tid = threadIdx.x;
    const int cx  = tid & 15;
    const int ry  = tid >> 4;       // 0..15 -> rows ry*8 .. ry*8+7
    const int rowBase = blockIdx.x * 128;

    float acc[8][4];
#pragma unroll
    for (int i = 0; i < 8; i++)
#pragma unroll
        for (int c = 0; c < 4; c++) acc[i][c] = 0.f;

    float as4[4], ad4[4];
#pragma unroll
    for (int c = 0; c < 4; c++) {
        as4[c] = att_src[cx * 4 + c];
        ad4[c] = att_dst[cx * 4 + c];
    }

    for (int kc = 0; kc < INF; kc += 32) {
#pragma unroll
        for (int idx = tid; idx < 128 * 32; idx += 256) {
            int r = idx >> 5, k = idx & 31;
            int gr = rowBase + r;
            xs[k][r] = (gr < N) ? x[(size_t)gr * INF + kc + k] : 0.f;
        }
#pragma unroll
        for (int idx = tid; idx < 32 * 64; idx += 256) {
            int k = idx >> 6, j = idx & 63;
            ws[k][j] = W[(size_t)(kc + k) * HID + j];
        }
        __syncthreads();

#pragma unroll
        for (int k = 0; k < 32; k++) {
            float4 wv = *(const float4*)&ws[k][cx * 4];
            float4 xa = *(const float4*)&xs[k][ry * 8];
            float4 xb = *(const float4*)&xs[k][ry * 8 + 4];
            float xv[8] = {xa.x, xa.y, xa.z, xa.w, xb.x, xb.y, xb.z, xb.w};
#pragma unroll
            for (int i = 0; i < 8; i++) {
                acc[i][0] += xv[i] * wv.x;
                acc[i][1] += xv[i] * wv.y;
                acc[i][2] += xv[i] * wv.z;
                acc[i][3] += xv[i] * wv.w;
            }
        }
        __syncthreads();
    }

#pragma unroll
    for (int i = 0; i < 8; i++) {
        int r = rowBase + ry * 8 + i;
        if (r < N) {
            __nv_bfloat162 p0 = __floats2bfloat162_rn(acc[i][0], acc[i][1]);
            __nv_bfloat162 p1 = __floats2bfloat162_rn(acc[i][2], acc[i][3]);
            uint2 pk;
            pk.x = *(const unsigned int*)&p0;
            pk.y = *(const unsigned int*)&p1;
            ((uint2*)g_hb)[(size_t)r * 16 + cx] = pk;

            float ps = acc[i][0] * as4[0] + acc[i][1] * as4[1] +
                       acc[i][2] * as4[2] + acc[i][3] * as4[3];
            float pd = acc[i][0] * ad4[0] + acc[i][1] * ad4[1] +
                       acc[i][2] * ad4[2] + acc[i][3] * ad4[3];
#pragma unroll
            for (int o = 8; o; o >>= 1) {   // reduce over the 16-lane cx group
                ps += __shfl_xor_sync(0xFFFFFFFFu, ps, o);
                pd += __shfl_xor_sync(0xFFFFFFFFu, pd, o);
            }
            if (cx == 0) { g_asrc[r] = ps; g_adst[r] = pd; }
        }
    }
}

// ---------------- single edge pass (bf16 gather, bf16x2 vector RED) ----------
// 8 lanes per edge (4 edges/warp). Lane sub: one LDG.128 of features
// sub*8..+7 and ONE red.global.add.noftz.v4.bf16x2 (16B) -> the 8 lanes form
// one contiguous 128B RED wavefront per edge (was 2x128B fp32).
// w = exp(leaky_relu(a_src[s]+a_dst[d])) (max-shift omitted: logits O(10),
// alpha shift-invariant, fp32-safe). denom[d] += w (fp32) from sub-lane 0.
__global__ __launch_bounds__(256) void edge_kernel(
    const int* __restrict__ ei, int E, int N)
{
    const int T = E + N;
    const int lane = threadIdx.x & 31;
    const int oct  = lane >> 3;
    const int sub  = lane & 7;

    long long warpId = ((long long)blockIdx.x * blockDim.x + threadIdx.x) >> 5;
    long long e = warpId * 4 + oct;
    if (e >= T) return;

    int s, d;
    if (e < E) { s = ei[e]; d = ei[E + e]; }
    else       { s = d = (int)(e - E); }

    float l = g_asrc[s] + g_adst[d];
    l = (l > 0.f) ? l : 0.2f * l;
    float w = expf(l);

    // 16B = 8 bf16 features sub*8 .. sub*8+7
    uint4 raw = __ldg(&((const uint4*)g_hb)[(size_t)s * 8 + sub]);
    const __nv_bfloat162* pr = (const __nv_bfloat162*)&raw;
    unsigned r0, r1, r2, r3;
    {
        float2 f;
        __nv_bfloat162 t;
        f = __bfloat1622float2(pr[0]); t = __floats2bfloat162_rn(w * f.x, w * f.y);
        r0 = *(const unsigned*)&t;
        f = __bfloat1622float2(pr[1]); t = __floats2bfloat162_rn(w * f.x, w * f.y);
        r1 = *(const unsigned*)&t;
        f = __bfloat1622float2(pr[2]); t = __floats2bfloat162_rn(w * f.x, w * f.y);
        r2 = *(const unsigned*)&t;
        f = __bfloat1622float2(pr[3]); t = __floats2bfloat162_rn(w * f.x, w * f.y);
        r3 = *(const unsigned*)&t;
    }

    __nv_bfloat16* ap = g_aggh + (size_t)d * HID + sub * 8;   // byte off sub*16
    asm volatile("red.global.add.noftz.v4.bf16x2 [%0], {%1, %2, %3, %4};"
                 :: "l"(ap), "r"(r0), "r"(r1), "r"(r2), "r"(r3) : "memory");

    if (sub == 0) atomicAdd(&g_denom[d], w);
}

// ---------------- colsum + fused final ---------------------------------------
// colsum of relu(agg/denom + bias) from bf16 agg; re-zeroes agg+denom.
// Last block computes out = (colsum/N) @ W_lin + b_lin, resets colsum+counter.
__global__ __launch_bounds__(256) void colsum_kernel(
    const float* __restrict__ bias,
    const float* __restrict__ W_lin, const float* __restrict__ b_lin,
    float* __restrict__ out, float invN, int N)
{
    const int c  = threadIdx.x & 7;     // uint4 group: features c*8 .. c*8+7
    const int rg = threadIdx.x >> 3;    // row sub-group 0..31
    const int lane = threadIdx.x & 31;
    const unsigned grpMask = 0xFFu << ((lane >> 3) * 8);  // my 8-thread group

    float bv[8];
#pragma unroll
    for (int i = 0; i < 8; i++) bv[i] = bias[c * 8 + i];

    float accv[8];
#pragma unroll
    for (int i = 0; i < 8; i++) accv[i] = 0.f;

    uint4* __restrict__ agg4 = (uint4*)g_aggh;
    const uint4 zero4 = make_uint4(0u, 0u, 0u, 0u);

    for (int r = blockIdx.x * 32 + rg; r < N; r += gridDim.x * 32) {
        float inv = 1.f / g_denom[r];
        size_t idx = (size_t)r * 8 + c;
        uint4 v = agg4[idx];
        agg4[idx] = zero4;                    // re-zero agg for next replay
        __syncwarp(grpMask);                  // all 8 have read denom[r]
        if (c == 0) g_denom[r] = 0.f;         // re-zero denom for next replay
        const __nv_bfloat162* pv = (const __nv_bfloat162*)&v;
#pragma unroll
        for (int i = 0; i < 4; i++) {
            float2 f = __bfloat1622float2(pv[i]);
            accv[2 * i]     += fmaxf(f.x * inv + bv[2 * i],     0.f);
            accv[2 * i + 1] += fmaxf(f.y * inv + bv[2 * i + 1], 0.f);
        }
    }

    __shared__ float sm[32][64];
#pragma unroll
    for (int i = 0; i < 8; i++) sm[rg][c * 8 + i] = accv[i];
    __syncthreads();
    if (threadIdx.x < 64) {
        float s = 0.f;
#pragma unroll
        for (int g = 0; g < 32; g++) s += sm[g][threadIdx.x];
        atomicAdd(&g_colsum[threadIdx.x], s);
    }

    // ---- last-block final matvec ----
    __shared__ bool isLast;
    __threadfence();
    __syncthreads();
    if (threadIdx.x == 0) {
        unsigned v = atomicAdd(&g_done, 1u);
        isLast = (v == gridDim.x - 1);
    }
    __syncthreads();
    if (isLast) {
        int j = threadIdx.x;
        if (j < 64) {
            float a = b_lin[j];
#pragma unroll
            for (int k = 0; k < 64; k++)
                a += (g_colsum[k] * invN) * W_lin[k * 64 + j];
            out[j] = a;
        }
        __syncthreads();
        if (j < 64) g_colsum[j] = 0.f;   // reset for next replay
        if (j == 0) g_done = 0u;          // reset counter
    }
}

// ---------------- launch -----------------------------------------------------
extern "C" void kernel_launch(void* const* d_in, const int* in_sizes, int n_in,
                              void* d_out, int out_size)
{
    const float* x       = (const float*)d_in[0];
    const int*   ei      = (const int*)d_in[1];
    const float* W       = (const float*)d_in[2];
    const float* att_src = (const float*)d_in[3];
    const float* att_dst = (const float*)d_in[4];
    const float* bias    = (const float*)d_in[5];
    const float* W_lin   = (const float*)d_in[6];
    const float* b_lin   = (const float*)d_in[7];
    float*       out     = (float*)d_out;

    const int N = in_sizes[0] / INF;       // 100000
    const int E = in_sizes[1] / 2;         // 1600000
    const int T = E + N;

    gemm_kernel<<<(N + 127) / 128, 256>>>(x, W, att_src, att_dst, N);

    long long warps = ((long long)T + 3) / 4;          // 4 edges per warp
    long long threads = warps * 32;
    int blocks = (int)((threads + 255) / 256);
    edge_kernel<<<blocks, 256>>>(ei, E, N);

    colsum_kernel<<<1024, 256>>>(bias, W_lin, b_lin, out, 1.0f / (float)N, N);
}